// round 1
// baseline (speedup 1.0000x reference)
#include <cuda_runtime.h>
#include <cstdint>

// Problem shape (fixed by the dataset)
constexpr int B = 8, C = 16, H = 512, W = 512;
constexpr int HW = H * W;            // 262144 = 2^18
constexpr int CHW = C * HW;
constexpr int NPIX = B * HW;         // 2,097,152
constexpr int NOUT = B * CHW;        // 33,554,432

// ---------------------------------------------------------------------------
// Zero-init output (d_out is poisoned to 0xAA by the harness)
// ---------------------------------------------------------------------------
__global__ __launch_bounds__(256) void zero_kernel(float4* __restrict__ out, int n4) {
    int i = blockIdx.x * 256 + threadIdx.x;
    if (i < n4) out[i] = make_float4(0.f, 0.f, 0.f, 0.f);
}

// ---------------------------------------------------------------------------
// Inverse bilinear splat.
// One thread per input pixel (b, h, w):
//   - compute the 4 target cells + bilinear weights once (shared across C)
//   - loop channels: coalesced x read, up to 4 RED.ADD.F32 per channel
// Boundary semantics: reference splats into a (H+3, W+3) padded buffer and
// slices [1:H+1, 1:W+1]; equivalently target (fi+di-1, fj+dj-1), drop OOB.
// relu(1-|gi-(fi+di)|) with fi=floor(gi) collapses to (1-frac, frac).
// ---------------------------------------------------------------------------
__global__ __launch_bounds__(256)
void splat_kernel(const float* __restrict__ x,
                  const float2* __restrict__ grid,
                  float* __restrict__ out) {
    int idx = blockIdx.x * 256 + threadIdx.x;
    if (idx >= NPIX) return;

    int b  = idx >> 18;        // / HW
    int hw = idx & (HW - 1);   // % HW

    float2 g = grid[idx];      // g.x -> i (height) coord, g.y -> j (width) coord

    // gi = clip((g+1)*0.5*H + 1, 0, H+1)   (H+1-2e-10 rounds to H+1 in f32)
    float gi = fminf(fmaxf((g.x + 1.0f) * 0.5f * (float)H + 1.0f, 0.0f), (float)(H + 1));
    float gj = fminf(fmaxf((g.y + 1.0f) * 0.5f * (float)W + 1.0f, 0.0f), (float)(W + 1));

    int   fi  = (int)gi;            // gi >= 0 so trunc == floor
    int   fj  = (int)gj;
    float fri = gi - (float)fi;     // in [0,1)
    float frj = gj - (float)fj;

    float w00 = (1.0f - fri) * (1.0f - frj);
    float w01 = (1.0f - fri) * frj;
    float w10 = fri * (1.0f - frj);
    float w11 = fri * frj;

    int oi0 = fi - 1;
    int oj0 = fj - 1;
    bool i0 = (unsigned)oi0       < (unsigned)H;
    bool i1 = (unsigned)(oi0 + 1) < (unsigned)H;
    bool j0 = (unsigned)oj0       < (unsigned)W;
    bool j1 = (unsigned)(oj0 + 1) < (unsigned)W;

    bool p00 = i0 && j0, p01 = i0 && j1, p10 = i1 && j0, p11 = i1 && j1;

    const float* xp = x   + (size_t)b * CHW + hw;
    float*       op = out + (size_t)b * CHW + oi0 * W + oj0;

#pragma unroll
    for (int c = 0; c < C; c++) {
        float v = __ldg(xp + c * HW);   // coalesced across the warp per channel
        float* o = op + c * HW;
        if (p00) atomicAdd(o,         v * w00);
        if (p01) atomicAdd(o + 1,     v * w01);
        if (p10) atomicAdd(o + W,     v * w10);
        if (p11) atomicAdd(o + W + 1, v * w11);
    }
}

extern "C" void kernel_launch(void* const* d_in, const int* in_sizes, int n_in,
                              void* d_out, int out_size) {
    const float*  x    = (const float*)d_in[0];
    const float2* grid = (const float2*)d_in[1];
    float*        out  = (float*)d_out;

    // 1) zero the output
    int n4 = NOUT / 4;
    zero_kernel<<<(n4 + 255) / 256, 256>>>((float4*)out, n4);

    // 2) splat
    splat_kernel<<<(NPIX + 255) / 256, 256>>>(x, grid, out);
}

// round 2
// speedup vs baseline: 2.3429x; 2.3429x over previous
#include <cuda_runtime.h>
#include <cstdint>

// Problem shape (fixed by the dataset)
constexpr int B = 8, C = 16, H = 512, W = 512;
constexpr int HW = H * W;            // 262144 = 2^18
constexpr int CHW = C * HW;
constexpr int NPIX = B * HW;         // 2,097,152
constexpr int NOUT = B * CHW;        // 33,554,432

// Channel-contiguous scratch accumulator, layout (B,H,W,C). 128 MiB.
// __device__ global = allowed scratch (no runtime allocation).
__device__ float g_scratch[NOUT];

// ---------------------------------------------------------------------------
// Zero the scratch (must run every launch: graph replays re-accumulate)
// ---------------------------------------------------------------------------
__global__ __launch_bounds__(256) void zero_kernel(float4* __restrict__ p, int n4) {
    int i = blockIdx.x * 256 + threadIdx.x;
    if (i < n4) p[i] = make_float4(0.f, 0.f, 0.f, 0.f);
}

// ---------------------------------------------------------------------------
// 16-byte vector reduction: one L2 request for 4 floats.
// ---------------------------------------------------------------------------
__device__ __forceinline__ void red_v4(float* p, float a, float b, float c, float d) {
    asm volatile("red.global.add.v4.f32 [%0], {%1, %2, %3, %4};"
                 :: "l"(p), "f"(a), "f"(b), "f"(c), "f"(d) : "memory");
}

// ---------------------------------------------------------------------------
// Inverse bilinear splat into (B,H,W,C) scratch.
// One thread per input pixel: 4 corners x 64 contiguous bytes (16 ch) each
// = 4 x (4 x red.v4) = 8 sector RMWs per pixel (vs 64 in the naive layout).
// ---------------------------------------------------------------------------
__global__ __launch_bounds__(256)
void splat_kernel(const float* __restrict__ x,
                  const float2* __restrict__ grid) {
    int idx = blockIdx.x * 256 + threadIdx.x;
    if (idx >= NPIX) return;

    int b  = idx >> 18;        // / HW
    int hw = idx & (HW - 1);   // % HW

    float2 g = grid[idx];      // g.x -> i (height), g.y -> j (width)

    float gi = fminf(fmaxf((g.x + 1.0f) * 0.5f * (float)H + 1.0f, 0.0f), (float)(H + 1));
    float gj = fminf(fmaxf((g.y + 1.0f) * 0.5f * (float)W + 1.0f, 0.0f), (float)(W + 1));

    int   fi  = (int)gi;            // gi >= 0 so trunc == floor
    int   fj  = (int)gj;
    float fri = gi - (float)fi;
    float frj = gj - (float)fj;

    float w00 = (1.0f - fri) * (1.0f - frj);
    float w01 = (1.0f - fri) * frj;
    float w10 = fri * (1.0f - frj);
    float w11 = fri * frj;

    int oi0 = fi - 1;
    int oj0 = fj - 1;
    bool i0 = (unsigned)oi0       < (unsigned)H;
    bool i1 = (unsigned)(oi0 + 1) < (unsigned)H;
    bool j0 = (unsigned)oj0       < (unsigned)W;
    bool j1 = (unsigned)(oj0 + 1) < (unsigned)W;

    // Load the 16 channel values (coalesced per channel across the warp)
    const float* xp = x + (size_t)b * CHW + hw;
    float v[C];
#pragma unroll
    for (int c = 0; c < C; c++) v[c] = __ldg(xp + c * HW);

    // Scratch base for this batch, (oi,oj) pixel -> base + (oi*W+oj)*C
    float* sb = g_scratch + (size_t)b * HW * C;
    float* o00 = sb + ((size_t)oi0 * W + oj0) * C;

#pragma unroll
    for (int k = 0; k < 4; k++) {
        int c4 = 4 * k;
        if (i0 && j0) red_v4(o00 + c4,
                             v[c4]*w00, v[c4+1]*w00, v[c4+2]*w00, v[c4+3]*w00);
        if (i0 && j1) red_v4(o00 + C + c4,
                             v[c4]*w01, v[c4+1]*w01, v[c4+2]*w01, v[c4+3]*w01);
        if (i1 && j0) red_v4(o00 + (size_t)W * C + c4,
                             v[c4]*w10, v[c4+1]*w10, v[c4+2]*w10, v[c4+3]*w10);
        if (i1 && j1) red_v4(o00 + (size_t)(W + 1) * C + c4,
                             v[c4]*w11, v[c4+1]*w11, v[c4+2]*w11, v[c4+3]*w11);
    }
}

// ---------------------------------------------------------------------------
// Transpose scratch (B,H,W,C) -> out (B,C,H,W). Fully overwrites d_out, so
// no separate output zero-init is needed.
// Block = 256 threads handles 256 consecutive pixels of one batch.
// ---------------------------------------------------------------------------
__global__ __launch_bounds__(256)
void transpose_kernel(const float* __restrict__ s, float* __restrict__ out) {
    __shared__ float sm[C][256 + 1];   // +1 pad: conflict-free both phases

    int base = blockIdx.x * 256;       // 256 | HW, so a block never straddles b
    int t = threadIdx.x;

    const float4* sp = (const float4*)(s + (size_t)(base + t) * C);
#pragma unroll
    for (int k = 0; k < 4; k++) {
        float4 f = sp[k];
        sm[4*k + 0][t] = f.x;
        sm[4*k + 1][t] = f.y;
        sm[4*k + 2][t] = f.z;
        sm[4*k + 3][t] = f.w;
    }
    __syncthreads();

    int b  = base >> 18;
    int hw = (base & (HW - 1)) + t;
    float* op = out + (size_t)b * CHW + hw;
#pragma unroll
    for (int c = 0; c < C; c++)
        op[(size_t)c * HW] = sm[c][t];   // coalesced 1 KiB row per block
}

extern "C" void kernel_launch(void* const* d_in, const int* in_sizes, int n_in,
                              void* d_out, int out_size) {
    const float*  x    = (const float*)d_in[0];
    const float2* grid = (const float2*)d_in[1];
    float*        out  = (float*)d_out;

    // Resolve the device-global scratch address host-side once per launch call
    // (cudaGetSymbolAddress is capture-safe: it does no device work).
    static float* scratch_ptr = nullptr;
    if (!scratch_ptr) cudaGetSymbolAddress((void**)&scratch_ptr, g_scratch);

    // 1) zero the scratch accumulator
    int n4 = NOUT / 4;
    zero_kernel<<<(n4 + 255) / 256, 256>>>((float4*)scratch_ptr, n4);

    // 2) splat into (B,H,W,C) scratch with 16B vector reductions
    splat_kernel<<<(NPIX + 255) / 256, 256>>>(x, grid);

    // 3) transpose scratch into the required (B,C,H,W) output
    transpose_kernel<<<NPIX / 256, 256>>>(scratch_ptr, out);
}

// round 3
// speedup vs baseline: 4.2001x; 1.7927x over previous
#include <cuda_runtime.h>
#include <cuda_fp16.h>
#include <cstdint>

// Problem shape (fixed by the dataset)
constexpr int B = 8, C = 16, H = 512, W = 512;
constexpr int HW = H * W;            // 262144 = 2^18
constexpr int CHW = C * HW;
constexpr int NPIX = B * HW;         // 2,097,152
constexpr int NOUT = B * CHW;        // 33,554,432

// Channel-contiguous fp16 scratch accumulator, layout (B,H,W,C). 64 MiB.
__device__ __half g_scratch[NOUT];

// ---------------------------------------------------------------------------
// 16-byte fp16 vector reduction: 8 half values per L2 sector-RMW slot.
// ---------------------------------------------------------------------------
__device__ __forceinline__ void red_v4h2(__half2* p, __half2 a, __half2 b,
                                         __half2 c, __half2 d) {
    unsigned ra = *(unsigned*)&a, rb = *(unsigned*)&b;
    unsigned rc = *(unsigned*)&c, rd = *(unsigned*)&d;
    asm volatile("red.global.add.noftz.v4.f16x2 [%0], {%1, %2, %3, %4};"
                 :: "l"(p), "r"(ra), "r"(rb), "r"(rc), "r"(rd) : "memory");
}

// ---------------------------------------------------------------------------
// Inverse bilinear splat into (B,H,W,C) fp16 scratch.
// One thread per input pixel: 4 corners x 32B (16 fp16 ch) = 8 RED ops/pixel
// (vs 16 in the f32 version) -> half the L2 atomic sector-RMW traffic.
// ---------------------------------------------------------------------------
__global__ __launch_bounds__(256)
void splat_kernel(const float* __restrict__ x,
                  const float2* __restrict__ grid) {
    int idx = blockIdx.x * 256 + threadIdx.x;
    if (idx >= NPIX) return;

    int b  = idx >> 18;        // / HW
    int hw = idx & (HW - 1);   // % HW

    float2 g = grid[idx];      // g.x -> i (height), g.y -> j (width)

    float gi = fminf(fmaxf((g.x + 1.0f) * 0.5f * (float)H + 1.0f, 0.0f), (float)(H + 1));
    float gj = fminf(fmaxf((g.y + 1.0f) * 0.5f * (float)W + 1.0f, 0.0f), (float)(W + 1));

    int   fi  = (int)gi;            // gi >= 0 so trunc == floor
    int   fj  = (int)gj;
    float fri = gi - (float)fi;
    float frj = gj - (float)fj;

    float w00 = (1.0f - fri) * (1.0f - frj);
    float w01 = (1.0f - fri) * frj;
    float w10 = fri * (1.0f - frj);
    float w11 = fri * frj;

    int oi0 = fi - 1;
    int oj0 = fj - 1;
    bool i0 = (unsigned)oi0       < (unsigned)H;
    bool i1 = (unsigned)(oi0 + 1) < (unsigned)H;
    bool j0 = (unsigned)oj0       < (unsigned)W;
    bool j1 = (unsigned)(oj0 + 1) < (unsigned)W;

    // Load the 16 channel values (coalesced per channel across the warp)
    const float* xp = x + (size_t)b * CHW + hw;
    float v[C];
#pragma unroll
    for (int c = 0; c < C; c++) v[c] = __ldg(xp + c * HW);

    // Scratch base for this batch: pixel (oi,oj) -> 16 contiguous halves (32B)
    __half* sb  = g_scratch + (size_t)b * HW * C;
    __half* o00 = sb + ((size_t)oi0 * W + oj0) * C;

    // Per corner: pack 16 weighted products into 8 half2, issue 2 v4.f16x2 REDs.
#define CORNER(pred, ptr, wgt)                                                  \
    if (pred) {                                                                 \
        __half2 h[8];                                                           \
        _Pragma("unroll")                                                       \
        for (int j = 0; j < 8; j++)                                             \
            h[j] = __floats2half2_rn(v[2*j] * (wgt), v[2*j+1] * (wgt));         \
        red_v4h2((__half2*)(ptr),     h[0], h[1], h[2], h[3]);                  \
        red_v4h2((__half2*)(ptr) + 4, h[4], h[5], h[6], h[7]);                  \
    }

    CORNER(i0 && j0, o00,                     w00)
    CORNER(i0 && j1, o00 + C,                 w01)
    CORNER(i1 && j0, o00 + (size_t)W * C,     w10)
    CORNER(i1 && j1, o00 + (size_t)(W+1) * C, w11)
#undef CORNER
}

// ---------------------------------------------------------------------------
// Transpose fp16 scratch (B,H,W,C) -> f32 out (B,C,H,W).
// Block = 128 threads, tile = 512 consecutive pixels (512 | HW).
// uint4 loads (32B/pixel in 2 reads), conflict-free smem, float4 stores.
// Fully overwrites d_out.
// ---------------------------------------------------------------------------
__global__ __launch_bounds__(128)
void transpose_kernel(const __half2* __restrict__ s, float* __restrict__ out) {
    __shared__ __half2 sm[8][512];   // sm[r][p] = channels (2r, 2r+1) of pixel p

    int base = blockIdx.x * 512;
    int t = threadIdx.x;

#pragma unroll
    for (int q = 0; q < 4; q++) {
        int p = t + 128 * q;
        const uint4* sp = (const uint4*)(s + (size_t)(base + p) * 8); // 32B/pixel
        uint4 a = sp[0], bq = sp[1];
        sm[0][p] = *(__half2*)&a.x;  sm[1][p] = *(__half2*)&a.y;
        sm[2][p] = *(__half2*)&a.z;  sm[3][p] = *(__half2*)&a.w;
        sm[4][p] = *(__half2*)&bq.x; sm[5][p] = *(__half2*)&bq.y;
        sm[6][p] = *(__half2*)&bq.z; sm[7][p] = *(__half2*)&bq.w;
    }
    __syncthreads();

    int b  = base >> 18;
    int hw = base & (HW - 1);
    float* ob = out + (size_t)b * CHW + hw;

#pragma unroll
    for (int r = 0; r < 8; r++) {
        // 16B smem read: 4 consecutive half2 of channel pair r
        uint4 raw = *(const uint4*)&sm[r][4 * t];
        float2 f0 = __half22float2(*(__half2*)&raw.x);
        float2 f1 = __half22float2(*(__half2*)&raw.y);
        float2 f2 = __half22float2(*(__half2*)&raw.z);
        float2 f3 = __half22float2(*(__half2*)&raw.w);
        float4 ve = make_float4(f0.x, f1.x, f2.x, f3.x);  // channel 2r
        float4 vo = make_float4(f0.y, f1.y, f2.y, f3.y);  // channel 2r+1
        ((float4*)(ob + (size_t)(2*r)     * HW))[t] = ve;
        ((float4*)(ob + (size_t)(2*r + 1) * HW))[t] = vo;
    }
}

extern "C" void kernel_launch(void* const* d_in, const int* in_sizes, int n_in,
                              void* d_out, int out_size) {
    const float*  x    = (const float*)d_in[0];
    const float2* grid = (const float2*)d_in[1];
    float*        out  = (float*)d_out;

    static __half* scratch_ptr = nullptr;
    if (!scratch_ptr) cudaGetSymbolAddress((void**)&scratch_ptr, g_scratch);

    // 1) zero the fp16 scratch (64 MiB; memset node is graph-capturable)
    cudaMemsetAsync(scratch_ptr, 0, (size_t)NOUT * sizeof(__half), 0);

    // 2) splat with 16B fp16 vector reductions (8 sector-RMWs per pixel)
    splat_kernel<<<(NPIX + 255) / 256, 256>>>(x, grid);

    // 3) transpose fp16 scratch into the f32 (B,C,H,W) output
    transpose_kernel<<<NPIX / 512, 128>>>((const __half2*)scratch_ptr, out);
}